// round 4
// baseline (speedup 1.0000x reference)
#include <cuda_runtime.h>
#include <cuda_bf16.h>
#include <cstdint>

// Inputs (metadata order):
//   d_in[0] features  float32 [E*5]
//   d_in[1] values    float32 [E]
//   d_in[2] a0_weight float32 [5]
//   d_in[3] rows      int32   [E]
//   d_in[4] num_nodes int32   [1]
// Output: float32 [num_nodes]

__global__ void zero_out_kernel(float4* __restrict__ out4, int n4) {
    int i = blockIdx.x * blockDim.x + threadIdx.x;
    int stride = gridDim.x * blockDim.x;
    for (; i < n4; i += stride)
        out4[i] = make_float4(0.f, 0.f, 0.f, 0.f);
}

__global__ void zero_tail_kernel(float* __restrict__ out, int start, int n) {
    int i = start + blockIdx.x * blockDim.x + threadIdx.x;
    if (i < n) out[i] = 0.f;
}

__device__ __forceinline__ float4 ldcs4f(const float4* p) { return __ldcs(p); }
__device__ __forceinline__ int4   ldcs4i(const int4* p)   { return __ldcs(p); }

// Process one quad (4 consecutive edges): 5+1+1 wide streaming loads, 4 REDGs.
__device__ __forceinline__ void do_quad(
    const float4* __restrict__ feat4,
    const float4* __restrict__ vals4,
    const int4*   __restrict__ rows4,
    float* __restrict__ out,
    float w0, float w1, float w2, float w3, float w4,
    int q)
{
    const float4 f0 = ldcs4f(feat4 + (size_t)q * 5 + 0);
    const float4 f1 = ldcs4f(feat4 + (size_t)q * 5 + 1);
    const float4 f2 = ldcs4f(feat4 + (size_t)q * 5 + 2);
    const float4 f3 = ldcs4f(feat4 + (size_t)q * 5 + 3);
    const float4 f4 = ldcs4f(feat4 + (size_t)q * 5 + 4);
    const float4 v  = ldcs4f(vals4 + q);
    const int4   r  = ldcs4i(rows4 + q);

    float d0 = w0*f0.x + w1*f0.y + w2*f0.z + w3*f0.w + w4*f1.x;
    float d1 = w0*f1.y + w1*f1.z + w2*f1.w + w3*f2.x + w4*f2.y;
    float d2 = w0*f2.z + w1*f2.w + w2*f3.x + w3*f3.y + w4*f3.z;
    float d3 = w0*f3.w + w1*f4.x + w2*f4.y + w3*f4.z + w4*f4.w;

    atomicAdd(out + r.x, v.x * d0);
    atomicAdd(out + r.y, v.y * d1);
    atomicAdd(out + r.z, v.z * d2);
    atomicAdd(out + r.w, v.w * d3);
}

// Persistent grid-stride kernel, 2 quads (8 edges) per iteration so ptxas can
// software-pipeline the next iteration's loads under this iteration's REDGs.
__global__ __launch_bounds__(256) void scatter_dot_vec4_kernel(
    const float4* __restrict__ feat4,  // [E*5/4]
    const float4* __restrict__ vals4,  // [E/4]
    const float*  __restrict__ w,      // [5]
    const int4*   __restrict__ rows4,  // [E/4]
    float* __restrict__ out,
    int nQuads)                        // E/4
{
    const float w0 = __ldg(w + 0);
    const float w1 = __ldg(w + 1);
    const float w2 = __ldg(w + 2);
    const float w3 = __ldg(w + 3);
    const float w4 = __ldg(w + 4);

    const int tid    = blockIdx.x * blockDim.x + threadIdx.x;
    const int stride = gridDim.x * blockDim.x;

    int q = tid;
    // Main loop: two quads per trip (strided so warps stay coalesced).
    for (; q + stride < nQuads; q += 2 * stride) {
        do_quad(feat4, vals4, rows4, out, w0, w1, w2, w3, w4, q);
        do_quad(feat4, vals4, rows4, out, w0, w1, w2, w3, w4, q + stride);
    }
    if (q < nQuads)
        do_quad(feat4, vals4, rows4, out, w0, w1, w2, w3, w4, q);
}

// Scalar tail for E % 4 != 0 (not hit for E = 2^24, kept for generality).
__global__ void scatter_dot_tail_kernel(
    const float* __restrict__ feat,
    const float* __restrict__ vals,
    const float* __restrict__ w,
    const int*   __restrict__ rows,
    float* __restrict__ out,
    int start, int E)
{
    int e = start + blockIdx.x * blockDim.x + threadIdx.x;
    if (e >= E) return;
    const float* f = feat + (size_t)e * 5;
    float d = vals[e] * (w[0]*f[0] + w[1]*f[1] + w[2]*f[2] + w[3]*f[3] + w[4]*f[4]);
    atomicAdd(out + rows[e], d);
}

extern "C" void kernel_launch(void* const* d_in, const int* in_sizes, int n_in,
                              void* d_out, int out_size)
{
    const float* feat = (const float*)d_in[0];
    const float* vals = (const float*)d_in[1];
    const float* w    = (const float*)d_in[2];
    const int*   rows = (const int*)d_in[3];
    float* out = (float*)d_out;

    const int E = in_sizes[1];          // values has E elements
    const int N = out_size;             // num_nodes

    // Zero the (poisoned) output.
    {
        int n4 = N / 4;
        int zb = 256;
        int zg = (n4 + zb - 1) / zb;
        if (zg > 4736) zg = 4736;
        if (n4 > 0) zero_out_kernel<<<zg, zb>>>((float4*)out, n4);
        if (N - n4 * 4 > 0)
            zero_tail_kernel<<<1, 32>>>(out, n4 * 4, N);
    }

    const int nQuads = E / 4;
    if (nQuads > 0) {
        const int threads = 256;
        // Persistent-ish: 6 blocks per SM keeps warps resident across ~9
        // iterations; grid-stride handles any E.
        int blocks = 148 * 6;
        int maxBlocks = (nQuads + threads - 1) / threads;
        if (blocks > maxBlocks) blocks = maxBlocks;
        scatter_dot_vec4_kernel<<<blocks, threads>>>(
            (const float4*)feat, (const float4*)vals, w, (const int4*)rows,
            out, nQuads);
    }
    const int tailStart = nQuads * 4;
    if (E - tailStart > 0) {
        int n = E - tailStart;
        scatter_dot_tail_kernel<<<(n + 255) / 256, 256>>>(
            feat, vals, w, rows, out, tailStart, E);
    }
}

// round 6
// speedup vs baseline: 1.1366x; 1.1366x over previous
#include <cuda_runtime.h>
#include <cuda_bf16.h>
#include <cstdint>

// Inputs (metadata order):
//   d_in[0] features  float32 [E*5]
//   d_in[1] values    float32 [E]
//   d_in[2] a0_weight float32 [5]
//   d_in[3] rows      int32   [E]
//   d_in[4] num_nodes int32   [1]
// Output: float32 [num_nodes]

__global__ void zero_out_kernel(float4* __restrict__ out4, int n4) {
    int i = blockIdx.x * blockDim.x + threadIdx.x;
    int stride = gridDim.x * blockDim.x;
    for (; i < n4; i += stride)
        out4[i] = make_float4(0.f, 0.f, 0.f, 0.f);
}

__global__ void zero_tail_kernel(float* __restrict__ out, int start, int n) {
    int i = start + blockIdx.x * blockDim.x + threadIdx.x;
    if (i < n) out[i] = 0.f;
}

// One-shot: each thread owns 4 consecutive edges (one "quad").
// All stream loads are evict-first (__ldcs) so the one-touch 485 MB stream
// does not evict the 12 MB L2-resident output that the atomics RMW.
__global__ __launch_bounds__(256) void scatter_dot_vec4_kernel(
    const float4* __restrict__ feat4,  // [E*5/4]
    const float4* __restrict__ vals4,  // [E/4]
    const float*  __restrict__ w,      // [5]
    const int4*   __restrict__ rows4,  // [E/4]
    float* __restrict__ out,
    int nQuads)                        // E/4
{
    const float w0 = __ldg(w + 0);
    const float w1 = __ldg(w + 1);
    const float w2 = __ldg(w + 2);
    const float w3 = __ldg(w + 3);
    const float w4 = __ldg(w + 4);

    int q = blockIdx.x * blockDim.x + threadIdx.x;
    if (q >= nQuads) return;

    // Front-batched wide streaming loads (max MLP).
    const float4 f0 = __ldcs(feat4 + (size_t)q * 5 + 0);
    const float4 f1 = __ldcs(feat4 + (size_t)q * 5 + 1);
    const float4 f2 = __ldcs(feat4 + (size_t)q * 5 + 2);
    const float4 f3 = __ldcs(feat4 + (size_t)q * 5 + 3);
    const float4 f4 = __ldcs(feat4 + (size_t)q * 5 + 4);
    const float4 v  = __ldcs(vals4 + q);
    const int4   r  = __ldcs(rows4 + q);

    // edge0: f0.x f0.y f0.z f0.w f1.x
    float d0 = w0*f0.x + w1*f0.y + w2*f0.z + w3*f0.w + w4*f1.x;
    // edge1: f1.y f1.z f1.w f2.x f2.y
    float d1 = w0*f1.y + w1*f1.z + w2*f1.w + w3*f2.x + w4*f2.y;
    // edge2: f2.z f2.w f3.x f3.y f3.z
    float d2 = w0*f2.z + w1*f2.w + w2*f3.x + w3*f3.y + w4*f3.z;
    // edge3: f3.w f4.x f4.y f4.z f4.w
    float d3 = w0*f3.w + w1*f4.x + w2*f4.y + w3*f4.z + w4*f4.w;

    atomicAdd(out + r.x, v.x * d0);
    atomicAdd(out + r.y, v.y * d1);
    atomicAdd(out + r.z, v.z * d2);
    atomicAdd(out + r.w, v.w * d3);
}

// Scalar tail for E % 4 != 0 (not hit for E = 2^24, kept for generality).
__global__ void scatter_dot_tail_kernel(
    const float* __restrict__ feat,
    const float* __restrict__ vals,
    const float* __restrict__ w,
    const int*   __restrict__ rows,
    float* __restrict__ out,
    int start, int E)
{
    int e = start + blockIdx.x * blockDim.x + threadIdx.x;
    if (e >= E) return;
    const float* f = feat + (size_t)e * 5;
    float d = vals[e] * (w[0]*f[0] + w[1]*f[1] + w[2]*f[2] + w[3]*f[3] + w[4]*f[4]);
    atomicAdd(out + rows[e], d);
}

extern "C" void kernel_launch(void* const* d_in, const int* in_sizes, int n_in,
                              void* d_out, int out_size)
{
    const float* feat = (const float*)d_in[0];
    const float* vals = (const float*)d_in[1];
    const float* w    = (const float*)d_in[2];
    const int*   rows = (const int*)d_in[3];
    float* out = (float*)d_out;

    const int E = in_sizes[1];          // values has E elements
    const int N = out_size;             // num_nodes

    // Zero the (poisoned) output.
    {
        int n4 = N / 4;
        int zb = 256;
        int zg = (n4 + zb - 1) / zb;
        if (zg > 8192) zg = 8192;
        if (n4 > 0) zero_out_kernel<<<zg, zb>>>((float4*)out, n4);
        if (N - n4 * 4 > 0)
            zero_tail_kernel<<<1, 32>>>(out, n4 * 4, N);
    }

    const int nQuads = E / 4;
    if (nQuads > 0) {
        const int threads = 256;
        const int blocks = (nQuads + threads - 1) / threads;
        scatter_dot_vec4_kernel<<<blocks, threads>>>(
            (const float4*)feat, (const float4*)vals, w, (const int4*)rows,
            out, nQuads);
    }
    const int tailStart = nQuads * 4;
    if (E - tailStart > 0) {
        int n = E - tailStart;
        scatter_dot_tail_kernel<<<(n + 255) / 256, 256>>>(
            feat, vals, w, rows, out, tailStart, E);
    }
}

// round 8
// speedup vs baseline: 1.1403x; 1.0033x over previous
#include <cuda_runtime.h>
#include <cuda_bf16.h>
#include <cstdint>

// Inputs (metadata order):
//   d_in[0] features  float32 [E*5]
//   d_in[1] values    float32 [E]
//   d_in[2] a0_weight float32 [5]
//   d_in[3] rows      int32   [E]
//   d_in[4] num_nodes int32   [1]
// Output: float32 [num_nodes]

__global__ void zero_out_kernel(float4* __restrict__ out4, int n4) {
    int i = blockIdx.x * blockDim.x + threadIdx.x;
    if (i < n4)
        out4[i] = make_float4(0.f, 0.f, 0.f, 0.f);
}

__global__ void zero_tail_kernel(float* __restrict__ out, int start, int n) {
    int i = start + blockIdx.x * blockDim.x + threadIdx.x;
    if (i < n) out[i] = 0.f;
}

// One-shot: each thread owns 4 consecutive edges (one "quad").
// 128-thread blocks: 13 resident blocks/SM (52 warps) and 2x finer block
// turnover than 256-thread blocks -> better LDG/REDG overlap in the LSU.
__global__ __launch_bounds__(128) void scatter_dot_vec4_kernel(
    const float4* __restrict__ feat4,  // [E*5/4]
    const float4* __restrict__ vals4,  // [E/4]
    const float*  __restrict__ w,      // [5]
    const int4*   __restrict__ rows4,  // [E/4]
    float* __restrict__ out,
    int nQuads)                        // E/4
{
    const float w0 = __ldg(w + 0);
    const float w1 = __ldg(w + 1);
    const float w2 = __ldg(w + 2);
    const float w3 = __ldg(w + 3);
    const float w4 = __ldg(w + 4);

    int q = blockIdx.x * blockDim.x + threadIdx.x;
    if (q >= nQuads) return;

    // Front-batched wide streaming loads (max MLP, one-touch -> evict-first).
    const float4 f0 = __ldcs(feat4 + (size_t)q * 5 + 0);
    const float4 f1 = __ldcs(feat4 + (size_t)q * 5 + 1);
    const float4 f2 = __ldcs(feat4 + (size_t)q * 5 + 2);
    const float4 f3 = __ldcs(feat4 + (size_t)q * 5 + 3);
    const float4 f4 = __ldcs(feat4 + (size_t)q * 5 + 4);
    const float4 v  = __ldcs(vals4 + q);
    const int4   r  = __ldcs(rows4 + q);

    // edge0: f0.x f0.y f0.z f0.w f1.x
    float d0 = w0*f0.x + w1*f0.y + w2*f0.z + w3*f0.w + w4*f1.x;
    // edge1: f1.y f1.z f1.w f2.x f2.y
    float d1 = w0*f1.y + w1*f1.z + w2*f1.w + w3*f2.x + w4*f2.y;
    // edge2: f2.z f2.w f3.x f3.y f3.z
    float d2 = w0*f2.z + w1*f2.w + w2*f3.x + w3*f3.y + w4*f3.z;
    // edge3: f3.w f4.x f4.y f4.z f4.w
    float d3 = w0*f3.w + w1*f4.x + w2*f4.y + w3*f4.z + w4*f4.w;

    atomicAdd(out + r.x, v.x * d0);
    atomicAdd(out + r.y, v.y * d1);
    atomicAdd(out + r.z, v.z * d2);
    atomicAdd(out + r.w, v.w * d3);
}

// Scalar tail for E % 4 != 0 (not hit for E = 2^24, kept for generality).
__global__ void scatter_dot_tail_kernel(
    const float* __restrict__ feat,
    const float* __restrict__ vals,
    const float* __restrict__ w,
    const int*   __restrict__ rows,
    float* __restrict__ out,
    int start, int E)
{
    int e = start + blockIdx.x * blockDim.x + threadIdx.x;
    if (e >= E) return;
    const float* f = feat + (size_t)e * 5;
    float d = vals[e] * (w[0]*f[0] + w[1]*f[1] + w[2]*f[2] + w[3]*f[3] + w[4]*f[4]);
    atomicAdd(out + rows[e], d);
}

extern "C" void kernel_launch(void* const* d_in, const int* in_sizes, int n_in,
                              void* d_out, int out_size)
{
    const float* feat = (const float*)d_in[0];
    const float* vals = (const float*)d_in[1];
    const float* w    = (const float*)d_in[2];
    const int*   rows = (const int*)d_in[3];
    float* out = (float*)d_out;

    const int E = in_sizes[1];          // values has E elements
    const int N = out_size;             // num_nodes

    // Zero the (poisoned) output.
    {
        int n4 = N / 4;
        int zb = 256;
        if (n4 > 0) {
            int zg = (n4 + zb - 1) / zb;
            zero_out_kernel<<<zg, zb>>>((float4*)out, n4);
        }
        if (N - n4 * 4 > 0)
            zero_tail_kernel<<<1, 32>>>(out, n4 * 4, N);
    }

    const int nQuads = E / 4;
    if (nQuads > 0) {
        const int threads = 128;
        const int blocks = (nQuads + threads - 1) / threads;
        scatter_dot_vec4_kernel<<<blocks, threads>>>(
            (const float4*)feat, (const float4*)vals, w, (const int4*)rows,
            out, nQuads);
    }
    const int tailStart = nQuads * 4;
    if (E - tailStart > 0) {
        int n = E - tailStart;
        scatter_dot_tail_kernel<<<(n + 255) / 256, 256>>>(
            feat, vals, w, rows, out, tailStart, E);
    }
}